// round 4
// baseline (speedup 1.0000x reference)
#include <cuda_runtime.h>
#include <math.h>

#define D    16
#define KNN  16
#define FULL 0xffffffffu

#define NMAX 30720
#define MMAX 8192
#define BUFCAP 192
#define KNN_BLK 64

// ---- scratch (static device globals; no allocation anywhere) ----
__device__ float4 g_atoms[MMAX];            // x,y,z,||y||^2
__device__ float  g_t[MMAX * D];            // transformed atom features
__device__ int    g_idx[NMAX * KNN];        // knn indices (set, arbitrary order)
__device__ float  g_rinv[NMAX * KNN];       // 1/dist^2 feature
__device__ float  g_S1[NMAX * D];           // per-point sum_k h1
__device__ float  g_S2[NMAX * D];           // per-point sum_k h2
__device__ float  g_part1[2048 * 32];       // BN1 block partials (sum[16],sumsq[16])
__device__ float  g_part2[512 * 32];        // BN2 block partials
__device__ float  g_bn[64];                 // sc1,sh1,sc2,sh2
__device__ int    g_ctr1 = 0;
__device__ int    g_ctr2 = 0;

__device__ __forceinline__ float leaky(float a) { return a > 0.f ? a : 0.2f * a; }

__device__ __forceinline__ unsigned fkey(float s) {
    unsigned b = __float_as_uint(s);
    b ^= ((unsigned)((int)b >> 31)) | 0x80000000u;   // monotonic map
    return b;
}

// ---------------------------------------------------------------------------
// K0: atom prep — 3-layer MLP on atom features + pack coords with norms
// ---------------------------------------------------------------------------
__global__ void prep_kernel(const float* __restrict__ atom_xyz,
                            const float* __restrict__ atom_types,
                            const float* __restrict__ Wt1, const float* __restrict__ bt1,
                            const float* __restrict__ Wt2, const float* __restrict__ bt2,
                            const float* __restrict__ Wt3, const float* __restrict__ bt3,
                            int M)
{
    __shared__ float sW[3][D * D];
    __shared__ float sB[3][D];
    int tid = threadIdx.x;
    for (int i = tid; i < D * D; i += blockDim.x) {
        sW[0][i] = Wt1[i];
        sW[1][i] = Wt2[i];
        sW[2][i] = Wt3[i];
    }
    if (tid < D) { sB[0][tid] = bt1[tid]; sB[1][tid] = bt2[tid]; sB[2][tid] = bt3[tid]; }
    __syncthreads();

    int i = blockIdx.x * blockDim.x + tid;
    if (i >= M) return;
    float x = atom_xyz[i * 3 + 0], y = atom_xyz[i * 3 + 1], z = atom_xyz[i * 3 + 2];
    g_atoms[i] = make_float4(x, y, z, x * x + y * y + z * z);

    float v[D], u[D];
#pragma unroll
    for (int j = 0; j < D; j++) v[j] = atom_types[i * D + j];
#pragma unroll
    for (int l = 0; l < 3; l++) {
#pragma unroll
        for (int j = 0; j < D; j++) {
            float a = sB[l][j];
#pragma unroll
            for (int kk = 0; kk < D; kk++) a = fmaf(v[kk], sW[l][kk * D + j], a);
            u[j] = leaky(a);
        }
#pragma unroll
        for (int j = 0; j < D; j++) v[j] = u[j];
    }
#pragma unroll
    for (int j = 0; j < D; j++) g_t[i * D + j] = v[j];
}

// ---------------------------------------------------------------------------
// K1: kNN — one THREAD per point. All lanes broadcast-read the same atom.
// Register-resident sorted 16 keys (monotonic u32), IMNMX bubble insert,
// warp-uniform activation via __any_sync. Candidate indices buffered in smem,
// filtered at the end against the final 16th key (order-free set recovery).
// ---------------------------------------------------------------------------
__global__ void __launch_bounds__(KNN_BLK) knn_kernel(const float* __restrict__ xyz,
                                                      int N, int M)
{
    __shared__ unsigned short buf[BUFCAP * KNN_BLK];   // entry-major: [c][tid]
    int raw = blockIdx.x * KNN_BLK + threadIdx.x;
    bool valid = raw < N;
    int i = valid ? raw : N - 1;

    const float px = xyz[i * 3 + 0], py = xyz[i * 3 + 1], pz = xyz[i * 3 + 2];
    const float cx = -2.f * px, cy = -2.f * py, cz = -2.f * pz;

    unsigned k[KNN];
#pragma unroll
    for (int j = 0; j < KNN; j++) k[j] = 0xFFFFFFFFu;
    int cnt = 0;

    int M4 = M & ~3;
#pragma unroll 1
    for (int a = 0; a < M4; a += 4) {
        unsigned u[4];
        bool ins[4];
#pragma unroll
        for (int q = 0; q < 4; q++) {
            float4 at = g_atoms[a + q];
            float s = fmaf(cx, at.x, at.w);
            s = fmaf(cy, at.y, s);
            s = fmaf(cz, at.z, s);
            u[q] = fkey(s);
            ins[q] = u[q] < k[KNN - 1];
        }
        if (__any_sync(FULL, ins[0] | ins[1] | ins[2] | ins[3])) {
#pragma unroll
            for (int q = 0; q < 4; q++) {
                if (__any_sync(FULL, ins[q])) {
                    unsigned v = ins[q] ? u[q] : 0xFFFFFFFFu;
                    k[KNN - 1] = min(k[KNN - 1], v);
#pragma unroll
                    for (int j = KNN - 1; j >= 1; j--) {
                        unsigned lo = min(k[j - 1], k[j]);
                        unsigned hi = max(k[j - 1], k[j]);
                        k[j - 1] = lo; k[j] = hi;
                    }
                    if (ins[q]) {
                        int c = cnt < BUFCAP ? cnt : BUFCAP - 1;
                        buf[c * KNN_BLK + threadIdx.x] = (unsigned short)(a + q);
                        cnt++;
                    }
                }
            }
        }
    }
    // scalar tail (M not multiple of 4)
    for (int a = M4; a < M; a++) {
        float4 at = g_atoms[a];
        float s = fmaf(cx, at.x, at.w);
        s = fmaf(cy, at.y, s);
        s = fmaf(cz, at.z, s);
        unsigned uu = fkey(s);
        bool ins = uu < k[KNN - 1];
        if (__any_sync(FULL, ins)) {
            unsigned v = ins ? uu : 0xFFFFFFFFu;
            k[KNN - 1] = min(k[KNN - 1], v);
#pragma unroll
            for (int j = KNN - 1; j >= 1; j--) {
                unsigned lo = min(k[j - 1], k[j]);
                unsigned hi = max(k[j - 1], k[j]);
                k[j - 1] = lo; k[j] = hi;
            }
            if (ins) {
                int c = cnt < BUFCAP ? cnt : BUFCAP - 1;
                buf[c * KNN_BLK + threadIdx.x] = (unsigned short)a;
                cnt++;
            }
        }
    }

    if (!valid) return;
    if (cnt > BUFCAP) cnt = BUFCAP;

    unsigned tau = k[KNN - 1];
    int out = 0;
    for (int c = 0; c < cnt && out < KNN; c++) {
        int a = buf[c * KNN_BLK + threadIdx.x];
        float4 at = g_atoms[a];
        float s = fmaf(cx, at.x, at.w);     // identical fp sequence -> identical key
        s = fmaf(cy, at.y, s);
        s = fmaf(cz, at.z, s);
        if (fkey(s) <= tau) {
            float dx = px - at.x, dy = py - at.y, dz = pz - at.z;
            float dd = fmaf(dz, dz, fmaf(dy, dy, dx * dx));
            g_idx[i * KNN + out]  = a;
            g_rinv[i * KNN + out] = 1.0f / dd;
            out++;
        }
    }
}

// ---------------------------------------------------------------------------
// K2: stats1 — row-parallel conv1->leaky, BN1 sum/sumsq partials only.
// Last block (atomic ticket) reduces partials and writes sc1/sh1 to g_bn.
// ---------------------------------------------------------------------------
__global__ void stats1_kernel(const float* __restrict__ W1, const float* __restrict__ b1,
                              const float* __restrict__ g1, const float* __restrict__ be1,
                              int NR, float inv_n)
{
    __shared__ float sW[(D + 1) * D];
    __shared__ float sb[D];
    __shared__ float red[8 * 32];
    __shared__ float tot[32];
    __shared__ int   ticket;
    int tid = threadIdx.x;
    for (int t = tid; t < (D + 1) * D; t += 256) sW[t] = W1[t];
    if (tid < D) sb[tid] = b1[tid];
    __syncthreads();

    int r = blockIdx.x * 256 + tid;
    float h[D];
#pragma unroll
    for (int j = 0; j < D; j++) h[j] = 0.f;

    if (r < NR) {
        int   ai = g_idx[r];
        float rv = g_rinv[r];
        const float4* tp = (const float4*)&g_t[ai * D];
        float f[D];
        *(float4*)&f[0]  = tp[0];
        *(float4*)&f[4]  = tp[1];
        *(float4*)&f[8]  = tp[2];
        *(float4*)&f[12] = tp[3];
        float a[D];
#pragma unroll
        for (int j = 0; j < D; j++) a[j] = sb[j];
#pragma unroll
        for (int kk = 0; kk < D; kk++) {
            float fv = f[kk];
            const float4* wr = (const float4*)&sW[kk * D];
            float4 w0 = wr[0], w1 = wr[1], w2 = wr[2], w3 = wr[3];
            a[0]  = fmaf(fv, w0.x, a[0]);  a[1]  = fmaf(fv, w0.y, a[1]);
            a[2]  = fmaf(fv, w0.z, a[2]);  a[3]  = fmaf(fv, w0.w, a[3]);
            a[4]  = fmaf(fv, w1.x, a[4]);  a[5]  = fmaf(fv, w1.y, a[5]);
            a[6]  = fmaf(fv, w1.z, a[6]);  a[7]  = fmaf(fv, w1.w, a[7]);
            a[8]  = fmaf(fv, w2.x, a[8]);  a[9]  = fmaf(fv, w2.y, a[9]);
            a[10] = fmaf(fv, w2.z, a[10]); a[11] = fmaf(fv, w2.w, a[11]);
            a[12] = fmaf(fv, w3.x, a[12]); a[13] = fmaf(fv, w3.y, a[13]);
            a[14] = fmaf(fv, w3.z, a[14]); a[15] = fmaf(fv, w3.w, a[15]);
        }
        {
            const float4* wr = (const float4*)&sW[D * D];
            float4 w0 = wr[0], w1 = wr[1], w2 = wr[2], w3 = wr[3];
            a[0]  = fmaf(rv, w0.x, a[0]);  a[1]  = fmaf(rv, w0.y, a[1]);
            a[2]  = fmaf(rv, w0.z, a[2]);  a[3]  = fmaf(rv, w0.w, a[3]);
            a[4]  = fmaf(rv, w1.x, a[4]);  a[5]  = fmaf(rv, w1.y, a[5]);
            a[6]  = fmaf(rv, w1.z, a[6]);  a[7]  = fmaf(rv, w1.w, a[7]);
            a[8]  = fmaf(rv, w2.x, a[8]);  a[9]  = fmaf(rv, w2.y, a[9]);
            a[10] = fmaf(rv, w2.z, a[10]); a[11] = fmaf(rv, w2.w, a[11]);
            a[12] = fmaf(rv, w3.x, a[12]); a[13] = fmaf(rv, w3.y, a[13]);
            a[14] = fmaf(rv, w3.z, a[14]); a[15] = fmaf(rv, w3.w, a[15]);
        }
#pragma unroll
        for (int j = 0; j < D; j++) h[j] = leaky(a[j]);
    }

    int lane = tid & 31, w = tid >> 5;
#pragma unroll
    for (int j = 0; j < D; j++) {
        float sv = h[j], qv = h[j] * h[j];
#pragma unroll
        for (int o = 16; o > 0; o >>= 1) {
            sv += __shfl_xor_sync(FULL, sv, o);
            qv += __shfl_xor_sync(FULL, qv, o);
        }
        if (lane == 0) { red[w * 32 + j] = sv; red[w * 32 + 16 + j] = qv; }
    }
    __syncthreads();
    if (tid < 32) {
        float acc = 0.f;
#pragma unroll
        for (int ww = 0; ww < 8; ww++) acc += red[ww * 32 + tid];
        g_part1[blockIdx.x * 32 + tid] = acc;
    }
    __threadfence();
    __syncthreads();
    if (tid == 0) ticket = atomicAdd(&g_ctr1, 1);
    __syncthreads();
    if (ticket == gridDim.x - 1) {
        // final reduce: 256 threads, col = tid&31, rows strided by 8
        int c = tid & 31, sl = tid >> 5;
        float acc = 0.f;
        for (int b = sl; b < gridDim.x; b += 8) acc += g_part1[b * 32 + c];
        __syncthreads();          // red reuse
        red[sl * 32 + c] = acc;
        __syncthreads();
        if (tid < 32) {
            float t2 = 0.f;
#pragma unroll
            for (int ww = 0; ww < 8; ww++) t2 += red[ww * 32 + tid];
            tot[tid] = t2;
        }
        __syncthreads();
        if (tid < 16) {
            float mean = tot[tid] * inv_n;
            float var  = tot[16 + tid] * inv_n - mean * mean;
            float sc   = g1[tid] * rsqrtf(var + 1e-5f);
            float sh   = be1[tid] - mean * sc;
            g_bn[tid]      = sc;
            g_bn[16 + tid] = sh;
        }
        if (tid == 0) g_ctr1 = 0;
    }
}

// ---------------------------------------------------------------------------
// K3: stats2 — per POINT: recompute conv1->leaky (h1), S1 += h1,
// y = bn1(h1), conv2->leaky (h2), S2 += h2, Q2 += h2^2. Stores S1,S2.
// BN2 partials + last-block finalize (sc2/sh2).
// ---------------------------------------------------------------------------
__global__ void __launch_bounds__(128) stats2_kernel(
    const float* __restrict__ W1, const float* __restrict__ b1,
    const float* __restrict__ W2, const float* __restrict__ b2,
    const float* __restrict__ g2, const float* __restrict__ be2,
    int N, float inv_n)
{
    __shared__ float sW1[(D + 1) * D], sb1[D];
    __shared__ float sW2[D * D], sb2[D], ssc[D], ssh[D];
    __shared__ float red[4 * 32];
    __shared__ float tot[32];
    __shared__ int   ticket;
    int tid = threadIdx.x;
    for (int t = tid; t < (D + 1) * D; t += 128) sW1[t] = W1[t];
    for (int t = tid; t < D * D; t += 128) sW2[t] = W2[t];
    if (tid < D) { sb1[tid] = b1[tid]; sb2[tid] = b2[tid];
                   ssc[tid] = g_bn[tid]; ssh[tid] = g_bn[16 + tid]; }
    __syncthreads();

    int i = blockIdx.x * 128 + tid;
    float S1[D], S2[D], Q2[D];
#pragma unroll
    for (int j = 0; j < D; j++) { S1[j] = 0.f; S2[j] = 0.f; Q2[j] = 0.f; }

    if (i < N) {
        for (int k = 0; k < KNN; k++) {
            int   ai = g_idx[i * KNN + k];
            float rv = g_rinv[i * KNN + k];
            const float4* tp = (const float4*)&g_t[ai * D];
            float f[D];
            *(float4*)&f[0]  = tp[0];
            *(float4*)&f[4]  = tp[1];
            *(float4*)&f[8]  = tp[2];
            *(float4*)&f[12] = tp[3];
            float a[D];
#pragma unroll
            for (int j = 0; j < D; j++) a[j] = sb1[j];
#pragma unroll
            for (int kk = 0; kk <= D; kk++) {
                float fv = (kk < D) ? f[kk] : rv;
                const float4* wr = (const float4*)&sW1[kk * D];
                float4 w0 = wr[0], w1 = wr[1], w2 = wr[2], w3 = wr[3];
                a[0]  = fmaf(fv, w0.x, a[0]);  a[1]  = fmaf(fv, w0.y, a[1]);
                a[2]  = fmaf(fv, w0.z, a[2]);  a[3]  = fmaf(fv, w0.w, a[3]);
                a[4]  = fmaf(fv, w1.x, a[4]);  a[5]  = fmaf(fv, w1.y, a[5]);
                a[6]  = fmaf(fv, w1.z, a[6]);  a[7]  = fmaf(fv, w1.w, a[7]);
                a[8]  = fmaf(fv, w2.x, a[8]);  a[9]  = fmaf(fv, w2.y, a[9]);
                a[10] = fmaf(fv, w2.z, a[10]); a[11] = fmaf(fv, w2.w, a[11]);
                a[12] = fmaf(fv, w3.x, a[12]); a[13] = fmaf(fv, w3.y, a[13]);
                a[14] = fmaf(fv, w3.z, a[14]); a[15] = fmaf(fv, w3.w, a[15]);
            }
            float y[D];
#pragma unroll
            for (int j = 0; j < D; j++) {
                float hv = leaky(a[j]);
                S1[j] += hv;
                y[j] = fmaf(hv, ssc[j], ssh[j]);
            }
            float c2[D];
#pragma unroll
            for (int j = 0; j < D; j++) c2[j] = sb2[j];
#pragma unroll
            for (int kk = 0; kk < D; kk++) {
                float fv = y[kk];
                const float4* wr = (const float4*)&sW2[kk * D];
                float4 w0 = wr[0], w1 = wr[1], w2 = wr[2], w3 = wr[3];
                c2[0]  = fmaf(fv, w0.x, c2[0]);  c2[1]  = fmaf(fv, w0.y, c2[1]);
                c2[2]  = fmaf(fv, w0.z, c2[2]);  c2[3]  = fmaf(fv, w0.w, c2[3]);
                c2[4]  = fmaf(fv, w1.x, c2[4]);  c2[5]  = fmaf(fv, w1.y, c2[5]);
                c2[6]  = fmaf(fv, w1.z, c2[6]);  c2[7]  = fmaf(fv, w1.w, c2[7]);
                c2[8]  = fmaf(fv, w2.x, c2[8]);  c2[9]  = fmaf(fv, w2.y, c2[9]);
                c2[10] = fmaf(fv, w2.z, c2[10]); c2[11] = fmaf(fv, w2.w, c2[11]);
                c2[12] = fmaf(fv, w3.x, c2[12]); c2[13] = fmaf(fv, w3.y, c2[13]);
                c2[14] = fmaf(fv, w3.z, c2[14]); c2[15] = fmaf(fv, w3.w, c2[15]);
            }
#pragma unroll
            for (int j = 0; j < D; j++) {
                float h2 = leaky(c2[j]);
                S2[j] += h2;
                Q2[j] = fmaf(h2, h2, Q2[j]);
            }
        }
        float4* o1 = (float4*)&g_S1[i * D];
        float4* o2 = (float4*)&g_S2[i * D];
        o1[0] = make_float4(S1[0], S1[1], S1[2], S1[3]);
        o1[1] = make_float4(S1[4], S1[5], S1[6], S1[7]);
        o1[2] = make_float4(S1[8], S1[9], S1[10], S1[11]);
        o1[3] = make_float4(S1[12], S1[13], S1[14], S1[15]);
        o2[0] = make_float4(S2[0], S2[1], S2[2], S2[3]);
        o2[1] = make_float4(S2[4], S2[5], S2[6], S2[7]);
        o2[2] = make_float4(S2[8], S2[9], S2[10], S2[11]);
        o2[3] = make_float4(S2[12], S2[13], S2[14], S2[15]);
    }

    int lane = tid & 31, w = tid >> 5;
#pragma unroll
    for (int j = 0; j < D; j++) {
        float sv = S2[j], qv = Q2[j];
#pragma unroll
        for (int o = 16; o > 0; o >>= 1) {
            sv += __shfl_xor_sync(FULL, sv, o);
            qv += __shfl_xor_sync(FULL, qv, o);
        }
        if (lane == 0) { red[w * 32 + j] = sv; red[w * 32 + 16 + j] = qv; }
    }
    __syncthreads();
    if (tid < 32) {
        float acc = 0.f;
#pragma unroll
        for (int ww = 0; ww < 4; ww++) acc += red[ww * 32 + tid];
        g_part2[blockIdx.x * 32 + tid] = acc;
    }
    __threadfence();
    __syncthreads();
    if (tid == 0) ticket = atomicAdd(&g_ctr2, 1);
    __syncthreads();
    if (ticket == gridDim.x - 1) {
        int c = tid & 31, sl = tid >> 2 & 7;     // 128 threads: 4 rows? use stride 4
        // simpler: threads 0..31 serially sum (few hundred partials)
        __syncthreads();
        if (tid < 32) {
            float acc = 0.f;
            for (int b = 0; b < (int)gridDim.x; b++) acc += g_part2[b * 32 + tid];
            tot[tid] = acc;
        }
        __syncthreads();
        if (tid < 16) {
            float mean = tot[tid] * inv_n;
            float var  = tot[16 + tid] * inv_n - mean * mean;
            float sc   = g2[tid] * rsqrtf(var + 1e-5f);
            float sh   = be2[tid] - mean * sc;
            g_bn[32 + tid] = sc;
            g_bn[48 + tid] = sh;
        }
        if (tid == 0) g_ctr2 = 0;
        (void)c; (void)sl;
    }
}

// ---------------------------------------------------------------------------
// K4: final — fx1 = sc1*S1 + K*sh1 ; fx2 = sc2*S2 + K*sh2 ; out = [fx1,fx2]@W3+b3
// ---------------------------------------------------------------------------
__global__ void final_kernel(const float* __restrict__ W3, const float* __restrict__ b3,
                             float* __restrict__ out, int N)
{
    __shared__ float sW[2 * D * D], sb[D], bn[64];
    int tid = threadIdx.x;
    for (int t = tid; t < 2 * D * D; t += 256) sW[t] = W3[t];
    if (tid < D) sb[tid] = b3[tid];
    if (tid < 64) bn[tid] = g_bn[tid];
    __syncthreads();

    int i = blockIdx.x * 256 + tid;
    if (i >= N) return;

    float fx[2 * D];
    {
        const float4* p1 = (const float4*)&g_S1[i * D];
        const float4* p2 = (const float4*)&g_S2[i * D];
        float s1[D], s2[D];
        *(float4*)&s1[0] = p1[0]; *(float4*)&s1[4] = p1[1];
        *(float4*)&s1[8] = p1[2]; *(float4*)&s1[12] = p1[3];
        *(float4*)&s2[0] = p2[0]; *(float4*)&s2[4] = p2[1];
        *(float4*)&s2[8] = p2[2]; *(float4*)&s2[12] = p2[3];
#pragma unroll
        for (int j = 0; j < D; j++) {
            fx[j]     = fmaf(s1[j], bn[j],      (float)KNN * bn[16 + j]);
            fx[D + j] = fmaf(s2[j], bn[32 + j], (float)KNN * bn[48 + j]);
        }
    }
    float a[D];
#pragma unroll
    for (int j = 0; j < D; j++) a[j] = sb[j];
#pragma unroll
    for (int kk = 0; kk < 2 * D; kk++) {
        float fv = fx[kk];
        const float4* wr = (const float4*)&sW[kk * D];
        float4 w0 = wr[0], w1 = wr[1], w2 = wr[2], w3 = wr[3];
        a[0]  = fmaf(fv, w0.x, a[0]);  a[1]  = fmaf(fv, w0.y, a[1]);
        a[2]  = fmaf(fv, w0.z, a[2]);  a[3]  = fmaf(fv, w0.w, a[3]);
        a[4]  = fmaf(fv, w1.x, a[4]);  a[5]  = fmaf(fv, w1.y, a[5]);
        a[6]  = fmaf(fv, w1.z, a[6]);  a[7]  = fmaf(fv, w1.w, a[7]);
        a[8]  = fmaf(fv, w2.x, a[8]);  a[9]  = fmaf(fv, w2.y, a[9]);
        a[10] = fmaf(fv, w2.z, a[10]); a[11] = fmaf(fv, w2.w, a[11]);
        a[12] = fmaf(fv, w3.x, a[12]); a[13] = fmaf(fv, w3.y, a[13]);
        a[14] = fmaf(fv, w3.z, a[14]); a[15] = fmaf(fv, w3.w, a[15]);
    }
    float4* po = (float4*)&out[i * D];
    po[0] = make_float4(a[0], a[1], a[2], a[3]);
    po[1] = make_float4(a[4], a[5], a[6], a[7]);
    po[2] = make_float4(a[8], a[9], a[10], a[11]);
    po[3] = make_float4(a[12], a[13], a[14], a[15]);
}

// ---------------------------------------------------------------------------
extern "C" void kernel_launch(void* const* d_in, const int* in_sizes, int n_in,
                              void* d_out, int out_size)
{
    const float* xyz        = (const float*)d_in[0];
    const float* atom_xyz   = (const float*)d_in[1];
    const float* atom_types = (const float*)d_in[2];
    const float* Wt1 = (const float*)d_in[3];
    const float* bt1 = (const float*)d_in[4];
    const float* Wt2 = (const float*)d_in[5];
    const float* bt2 = (const float*)d_in[6];
    const float* Wt3 = (const float*)d_in[7];
    const float* bt3 = (const float*)d_in[8];
    const float* W1  = (const float*)d_in[9];
    const float* b1  = (const float*)d_in[10];
    const float* W2  = (const float*)d_in[11];
    const float* b2  = (const float*)d_in[12];
    const float* W3  = (const float*)d_in[13];
    const float* b3  = (const float*)d_in[14];
    const float* g1  = (const float*)d_in[15];
    const float* be1 = (const float*)d_in[16];
    const float* g2  = (const float*)d_in[17];
    const float* be2 = (const float*)d_in[18];

    int N = in_sizes[0] / 3;
    int M = in_sizes[1] / 3;

    prep_kernel<<<(M + 255) / 256, 256>>>(atom_xyz, atom_types,
                                          Wt1, bt1, Wt2, bt2, Wt3, bt3, M);

    knn_kernel<<<(N + KNN_BLK - 1) / KNN_BLK, KNN_BLK>>>(xyz, N, M);

    int NR = N * KNN;
    stats1_kernel<<<(NR + 255) / 256, 256>>>(W1, b1, g1, be1, NR, 1.0f / (float)NR);

    stats2_kernel<<<(N + 127) / 128, 128>>>(W1, b1, W2, b2, g2, be2,
                                            N, 1.0f / (float)NR);

    final_kernel<<<(N + 255) / 256, 256>>>(W3, b3, (float*)d_out, N);
}

// round 8
// speedup vs baseline: 1.0257x; 1.0257x over previous
#include <cuda_runtime.h>
#include <math.h>

#define D    16
#define KNN  16
#define FULL 0xffffffffu

#define NMAX 30720
#define MMAX 8192

// ---- scratch (static device globals; no allocation anywhere) ----
__device__ float4 g_atoms[MMAX];            // x,y,z,||y||^2
__device__ float  g_t[MMAX * D];            // transformed atom features
__device__ int    g_idx[NMAX * KNN];        // knn indices (set; order = JAX-compatible)
__device__ float  g_rinv[NMAX * KNN];       // 1/dist^2 feature
__device__ float  g_S1[NMAX * D];           // per-point sum_k h1
__device__ float  g_S2[NMAX * D];           // per-point sum_k h2
__device__ float  g_part1[2048 * 32];       // BN1 block partials (sum[16],sumsq[16])
__device__ float  g_part2[2048 * 32];       // BN2 block partials
__device__ float  g_bn[64];                 // sc1,sh1,sc2,sh2
__device__ int    g_ctr1 = 0;
__device__ int    g_ctr2 = 0;

__device__ __forceinline__ unsigned fkey(float s) {
    unsigned b = __float_as_uint(s);
    return b ^ (((unsigned)((int)b >> 31)) | 0x80000000u);   // monotonic map
}

// ---------------------------------------------------------------------------
// K0: prep — channel-per-lane 3-layer MLP on atoms + pack coords/norms.
// 16-lane half per atom; lane j owns channel j. ~12 regs.
// ---------------------------------------------------------------------------
__global__ __launch_bounds__(256) void prep_kernel(
    const float* __restrict__ atom_xyz, const float* __restrict__ atom_types,
    const float* __restrict__ Wt1, const float* __restrict__ bt1,
    const float* __restrict__ Wt2, const float* __restrict__ bt2,
    const float* __restrict__ Wt3, const float* __restrict__ bt3, int M)
{
    __shared__ float sW[3 * D * D];
    __shared__ float sB[3 * D];
    int tid = threadIdx.x;
    for (int t = tid; t < D * D; t += 256) {
        sW[t] = Wt1[t]; sW[256 + t] = Wt2[t]; sW[512 + t] = Wt3[t];
    }
    if (tid < D) { sB[tid] = bt1[tid]; sB[16 + tid] = bt2[tid]; sB[32 + tid] = bt3[tid]; }
    __syncthreads();

    int lane = tid & 31, j = lane & 15, half = lane >> 4;
    int i = blockIdx.x * 16 + (tid >> 5) * 2 + half;
    bool valid = i < M;
    int ii = valid ? i : M - 1;

    float v = atom_types[ii * D + j];
#pragma unroll
    for (int l = 0; l < 3; l++) {
        float a = sB[l * 16 + j];
#pragma unroll
        for (int kk = 0; kk < D; kk++)
            a = fmaf(__shfl_sync(FULL, v, kk, 16), sW[l * 256 + kk * D + j], a);
        v = a > 0.f ? a : 0.2f * a;
    }
    if (valid) {
        g_t[i * D + j] = v;
        if (j == 0) {
            float x = atom_xyz[i * 3 + 0], y = atom_xyz[i * 3 + 1], z = atom_xyz[i * 3 + 2];
            g_atoms[i] = make_float4(x, y, z, x * x + y * y + z * z);
        }
    }
}

// ---------------------------------------------------------------------------
// K1: kNN — warp per point. Lane-local sorted top-16 keys (parallel select
// network, no shuffles in hot loop). Bitonic tree-merge across lanes gives
// all lanes the exact global sorted 16. Rescan recovers indices against tau
// with exact tie handling (lowest indices first). ~28 regs.
// ---------------------------------------------------------------------------
__global__ __launch_bounds__(64) void knn_kernel(const float* __restrict__ xyz,
                                                 int N, int M)
{
    int w = (blockIdx.x * 64 + threadIdx.x) >> 5;   // point index
    int lane = threadIdx.x & 31;
    if (w >= N) return;

    const float px = xyz[w * 3 + 0], py = xyz[w * 3 + 1], pz = xyz[w * 3 + 2];
    const float cx = -2.f * px, cy = -2.f * py, cz = -2.f * pz;

    unsigned k[16];
#pragma unroll
    for (int j = 0; j < 16; j++) k[j] = 0xFFFFFFFFu;

    // phase 1: lane-local top-16 of lane's substream
    for (int base = 0; base < M; base += 32) {
        int a = base + lane;
        int aa = a < M ? a : M - 1;
        float4 at = g_atoms[aa];
        float s = fmaf(cx, at.x, at.w);
        s = fmaf(cy, at.y, s);
        s = fmaf(cz, at.z, s);
        unsigned v = (a < M) ? fkey(s) : 0xFFFFFFFFu;
        // parallel insertion into sorted list (descending j reads old k[j-1])
#pragma unroll
        for (int j = 15; j >= 1; j--) {
            unsigned t = v < k[j - 1] ? k[j - 1] : v;     // max(v, k[j-1])
            k[j] = v < k[j] ? t : k[j];
        }
        k[0] = v < k[0] ? v : k[0];
    }

    // phase 2: tree merge — after 5 levels every lane holds global sorted 16
#pragma unroll
    for (int m = 1; m < 32; m <<= 1) {
#pragma unroll
        for (int i2 = 0; i2 < 8; i2++) {
            unsigned plo = __shfl_xor_sync(FULL, k[i2], m);
            unsigned phi = __shfl_xor_sync(FULL, k[15 - i2], m);
            k[i2]      = min(k[i2],      phi);
            k[15 - i2] = min(k[15 - i2], plo);
        }
        // bitonic clean (input is bitonic -> sorted ascending)
#pragma unroll
        for (int d = 8; d >= 1; d >>= 1) {
#pragma unroll
            for (int i2 = 0; i2 < 16; i2++) {
                if ((i2 & d) == 0) {
                    unsigned lo = min(k[i2], k[i2 + d]);
                    unsigned hi = max(k[i2], k[i2 + d]);
                    k[i2] = lo; k[i2 + d] = hi;
                }
            }
        }
    }

    unsigned tau = k[15];
    int c_less = 0;
#pragma unroll
    for (int j = 0; j < 15; j++) c_less += (k[j] < tau) ? 1 : 0;
    int budget = 16 - c_less;

    // phase 3: rescan — emit all keys < tau (there are c_less of them, in
    // index order) then keys == tau lowest-index-first until 16 filled.
    int c_lt = 0, c_eq = 0;
    unsigned lmask = (1u << lane) - 1u;
    for (int base = 0; base < M; base += 32) {
        int a = base + lane;
        int aa = a < M ? a : M - 1;
        float4 at = g_atoms[aa];
        float s = fmaf(cx, at.x, at.w);
        s = fmaf(cy, at.y, s);
        s = fmaf(cz, at.z, s);
        unsigned v = (a < M) ? fkey(s) : 0xFFFFFFFFu;
        bool lt = v < tau;
        bool eq = v == tau;
        unsigned bl = __ballot_sync(FULL, lt);
        unsigned be = __ballot_sync(FULL, eq);
        int slot = -1;
        if (lt) {
            slot = c_lt + __popc(bl & lmask);
        } else if (eq) {
            int er = c_eq + __popc(be & lmask);
            if (er < budget) slot = c_less + er;
        }
        if (slot >= 0) {
            float dx = px - at.x, dy = py - at.y, dz = pz - at.z;
            float dd = fmaf(dz, dz, fmaf(dy, dy, dx * dx));
            g_idx[w * KNN + slot]  = a;
            g_rinv[w * KNN + slot] = 1.0f / dd;
        }
        c_lt += __popc(bl);
        c_eq += __popc(be);
    }
}

// ---------------------------------------------------------------------------
// K2: stats1 — channel-per-lane conv1->leaky, BN1 sum/sumsq; ticket finalize.
// 16-lane half per point; lane j owns channel j. ~16 regs.
// ---------------------------------------------------------------------------
__global__ __launch_bounds__(256) void stats1_kernel(
    const float* __restrict__ W1, const float* __restrict__ b1,
    const float* __restrict__ g1, const float* __restrict__ be1,
    int N, float inv_n)
{
    __shared__ float sW[(D + 1) * D];
    __shared__ float red[8 * 32];
    __shared__ float tot[32];
    __shared__ int   ticket;
    int tid = threadIdx.x;
    for (int t = tid; t < (D + 1) * D; t += 256) sW[t] = W1[t];
    __syncthreads();

    int lane = tid & 31, j = lane & 15, half = lane >> 4;
    int i = blockIdx.x * 16 + (tid >> 5) * 2 + half;
    bool valid = i < N;
    int ii = valid ? i : N - 1;
    float b1j = b1[j];

    float s = 0.f, q = 0.f;
#pragma unroll 1
    for (int k = 0; k < KNN; k++) {
        int   ai = g_idx[ii * KNN + k];
        float rv = g_rinv[ii * KNN + k];
        float f  = g_t[ai * D + j];
        float a  = b1j;
#pragma unroll
        for (int kk = 0; kk < D; kk++)
            a = fmaf(__shfl_sync(FULL, f, kk, 16), sW[kk * D + j], a);
        a = fmaf(rv, sW[D * D + j], a);
        float h = a > 0.f ? a : 0.2f * a;
        s += h;
        q = fmaf(h, h, q);
    }
    if (!valid) { s = 0.f; q = 0.f; }
    s += __shfl_xor_sync(FULL, s, 16);
    q += __shfl_xor_sync(FULL, q, 16);
    if (lane < 16) { red[(tid >> 5) * 32 + j] = s; red[(tid >> 5) * 32 + 16 + j] = q; }
    __syncthreads();
    if (tid < 32) {
        float acc = 0.f;
#pragma unroll
        for (int ww = 0; ww < 8; ww++) acc += red[ww * 32 + tid];
        g_part1[blockIdx.x * 32 + tid] = acc;
    }
    __threadfence();
    __syncthreads();
    if (tid == 0) ticket = atomicAdd(&g_ctr1, 1);
    __syncthreads();
    if (ticket == gridDim.x - 1) {
        int c = tid & 31, sl = tid >> 5;
        float acc = 0.f;
        for (int b = sl; b < (int)gridDim.x; b += 8) acc += g_part1[b * 32 + c];
        __syncthreads();
        red[sl * 32 + c] = acc;
        __syncthreads();
        if (tid < 32) {
            float t2 = 0.f;
#pragma unroll
            for (int ww = 0; ww < 8; ww++) t2 += red[ww * 32 + tid];
            tot[tid] = t2;
        }
        __syncthreads();
        if (tid < 16) {
            float mean = tot[tid] * inv_n;
            float var  = tot[16 + tid] * inv_n - mean * mean;
            float sc   = g1[tid] * rsqrtf(var + 1e-5f);
            g_bn[tid]      = sc;
            g_bn[16 + tid] = be1[tid] - mean * sc;
        }
        if (tid == 0) g_ctr1 = 0;
    }
}

// ---------------------------------------------------------------------------
// K3: stats2 — channel-per-lane conv1->bn1->conv2; S1,S2 per point; BN2
// sum/sumsq with ticket finalize. ~20 regs.
// ---------------------------------------------------------------------------
__global__ __launch_bounds__(256) void stats2_kernel(
    const float* __restrict__ W1, const float* __restrict__ b1,
    const float* __restrict__ W2, const float* __restrict__ b2,
    const float* __restrict__ g2, const float* __restrict__ be2,
    int N, float inv_n)
{
    __shared__ float sW1[(D + 1) * D];
    __shared__ float sW2[D * D];
    __shared__ float red[8 * 32];
    __shared__ float tot[32];
    __shared__ int   ticket;
    int tid = threadIdx.x;
    for (int t = tid; t < (D + 1) * D; t += 256) sW1[t] = W1[t];
    for (int t = tid; t < D * D; t += 256) sW2[t] = W2[t];
    __syncthreads();

    int lane = tid & 31, j = lane & 15, half = lane >> 4;
    int i = blockIdx.x * 16 + (tid >> 5) * 2 + half;
    bool valid = i < N;
    int ii = valid ? i : N - 1;
    float b1j = b1[j], b2j = b2[j];
    float sc1 = g_bn[j], sh1 = g_bn[16 + j];

    float S1 = 0.f, S2 = 0.f, Q2 = 0.f;
#pragma unroll 1
    for (int k = 0; k < KNN; k++) {
        int   ai = g_idx[ii * KNN + k];
        float rv = g_rinv[ii * KNN + k];
        float f  = g_t[ai * D + j];
        float a  = b1j;
#pragma unroll
        for (int kk = 0; kk < D; kk++)
            a = fmaf(__shfl_sync(FULL, f, kk, 16), sW1[kk * D + j], a);
        a = fmaf(rv, sW1[D * D + j], a);
        float h = a > 0.f ? a : 0.2f * a;
        S1 += h;
        float y = fmaf(h, sc1, sh1);
        float c = b2j;
#pragma unroll
        for (int kk = 0; kk < D; kk++)
            c = fmaf(__shfl_sync(FULL, y, kk, 16), sW2[kk * D + j], c);
        float h2 = c > 0.f ? c : 0.2f * c;
        S2 += h2;
        Q2 = fmaf(h2, h2, Q2);
    }
    if (valid) {
        g_S1[i * D + j] = S1;
        g_S2[i * D + j] = S2;
    } else { S2 = 0.f; Q2 = 0.f; }

    float s = S2 + __shfl_xor_sync(FULL, S2, 16);
    float q = Q2 + __shfl_xor_sync(FULL, Q2, 16);
    if (lane < 16) { red[(tid >> 5) * 32 + j] = s; red[(tid >> 5) * 32 + 16 + j] = q; }
    __syncthreads();
    if (tid < 32) {
        float acc = 0.f;
#pragma unroll
        for (int ww = 0; ww < 8; ww++) acc += red[ww * 32 + tid];
        g_part2[blockIdx.x * 32 + tid] = acc;
    }
    __threadfence();
    __syncthreads();
    if (tid == 0) ticket = atomicAdd(&g_ctr2, 1);
    __syncthreads();
    if (ticket == gridDim.x - 1) {
        int c = tid & 31, sl = tid >> 5;
        float acc = 0.f;
        for (int b = sl; b < (int)gridDim.x; b += 8) acc += g_part2[b * 32 + c];
        __syncthreads();
        red[sl * 32 + c] = acc;
        __syncthreads();
        if (tid < 32) {
            float t2 = 0.f;
#pragma unroll
            for (int ww = 0; ww < 8; ww++) t2 += red[ww * 32 + tid];
            tot[tid] = t2;
        }
        __syncthreads();
        if (tid < 16) {
            float mean = tot[tid] * inv_n;
            float var  = tot[16 + tid] * inv_n - mean * mean;
            float sc   = g2[tid] * rsqrtf(var + 1e-5f);
            g_bn[32 + tid] = sc;
            g_bn[48 + tid] = be2[tid] - mean * sc;
        }
        if (tid == 0) g_ctr2 = 0;
    }
}

// ---------------------------------------------------------------------------
// K4: final — fx1 = sc1*S1 + K*sh1; fx2 = sc2*S2 + K*sh2; out=[fx1,fx2]@W3+b3.
// Channel-per-lane. ~12 regs.
// ---------------------------------------------------------------------------
__global__ __launch_bounds__(256) void final_kernel(
    const float* __restrict__ W3, const float* __restrict__ b3,
    float* __restrict__ out, int N)
{
    __shared__ float sW[2 * D * D];
    int tid = threadIdx.x;
    for (int t = tid; t < 2 * D * D; t += 256) sW[t] = W3[t];
    __syncthreads();

    int lane = tid & 31, j = lane & 15, half = lane >> 4;
    int i = blockIdx.x * 16 + (tid >> 5) * 2 + half;
    bool valid = i < N;
    int ii = valid ? i : N - 1;

    float fx1 = fmaf(g_S1[ii * D + j], g_bn[j],      (float)KNN * g_bn[16 + j]);
    float fx2 = fmaf(g_S2[ii * D + j], g_bn[32 + j], (float)KNN * g_bn[48 + j]);
    float o = b3[j];
#pragma unroll
    for (int kk = 0; kk < D; kk++)
        o = fmaf(__shfl_sync(FULL, fx1, kk, 16), sW[kk * D + j], o);
#pragma unroll
    for (int kk = 0; kk < D; kk++)
        o = fmaf(__shfl_sync(FULL, fx2, kk, 16), sW[(D + kk) * D + j], o);
    if (valid) out[i * D + j] = o;
}

// ---------------------------------------------------------------------------
extern "C" void kernel_launch(void* const* d_in, const int* in_sizes, int n_in,
                              void* d_out, int out_size)
{
    const float* xyz        = (const float*)d_in[0];
    const float* atom_xyz   = (const float*)d_in[1];
    const float* atom_types = (const float*)d_in[2];
    const float* Wt1 = (const float*)d_in[3];
    const float* bt1 = (const float*)d_in[4];
    const float* Wt2 = (const float*)d_in[5];
    const float* bt2 = (const float*)d_in[6];
    const float* Wt3 = (const float*)d_in[7];
    const float* bt3 = (const float*)d_in[8];
    const float* W1  = (const float*)d_in[9];
    const float* b1  = (const float*)d_in[10];
    const float* W2  = (const float*)d_in[11];
    const float* b2  = (const float*)d_in[12];
    const float* W3  = (const float*)d_in[13];
    const float* b3  = (const float*)d_in[14];
    const float* g1  = (const float*)d_in[15];
    const float* be1 = (const float*)d_in[16];
    const float* g2  = (const float*)d_in[17];
    const float* be2 = (const float*)d_in[18];

    int N = in_sizes[0] / 3;
    int M = in_sizes[1] / 3;
    float inv_n = 1.0f / (float)(N * KNN);

    prep_kernel<<<(M + 15) / 16, 256>>>(atom_xyz, atom_types,
                                        Wt1, bt1, Wt2, bt2, Wt3, bt3, M);

    knn_kernel<<<(N + 1) / 2, 64>>>(xyz, N, M);

    int nb = (N + 15) / 16;
    stats1_kernel<<<nb, 256>>>(W1, b1, g1, be1, N, inv_n);
    stats2_kernel<<<nb, 256>>>(W1, b1, W2, b2, g2, be2, N, inv_n);
    final_kernel<<<nb, 256>>>(W3, b3, (float*)d_out, N);
}

// round 9
// speedup vs baseline: 2.8268x; 2.7560x over previous
#include <cuda_runtime.h>
#include <math.h>

#define D    16
#define KNN  16
#define FULL 0xffffffffu

#define NMAX 30720
#define MMAX 8192

#define G      24
#define NCELLS (G * G * G)        // 13824
#define HCELL  0.4f
#define GLO    (-4.8f)

// ---- scratch (static device globals; no allocation anywhere) ----
__device__ float4 g_atoms[MMAX];          // x,y,z,||y||^2 (original order)
__device__ float  g_u[MMAX * D];          // t @ W1[0:16,:]  (original order)
__device__ int    g_cellid[MMAX];
__device__ int    g_hist[NCELLS];
__device__ int    g_cellstart[NCELLS + 1];
__device__ int    g_cursor[NCELLS];
__device__ float4 g_satoms[MMAX];         // sorted by cell
__device__ int    g_sorig[MMAX];          // sorted -> original idx
__device__ int    g_idx[NMAX * KNN];      // knn ORIGINAL indices
__device__ float  g_rinv[NMAX * KNN];     // 1/dist^2 feature
__device__ float  g_S1[NMAX * D];
__device__ float  g_S2[NMAX * D];
__device__ float  g_part1[2048 * 32];
__device__ float  g_part2[2048 * 32];
__device__ float  g_bn[64];               // sc1,sh1,sc2,sh2
__device__ int    g_ctr1 = 0;
__device__ int    g_ctr2 = 0;

__device__ __forceinline__ unsigned fkey(float s) {
    unsigned b = __float_as_uint(s);
    return b ^ (((unsigned)((int)b >> 31)) | 0x80000000u);   // monotonic map
}

// ---------------------------------------------------------------------------
__global__ __launch_bounds__(256) void zero_kernel()
{
    int i = blockIdx.x * 256 + threadIdx.x;
    if (i < NCELLS) g_hist[i] = 0;
}

// ---------------------------------------------------------------------------
// prep: atom MLP -> t; u = t @ W1[0:16,:]; pack coords/norm; cell id + hist.
// 16-lane half per atom, lane j owns channel j.
// ---------------------------------------------------------------------------
__global__ __launch_bounds__(256) void prep_kernel(
    const float* __restrict__ atom_xyz, const float* __restrict__ atom_types,
    const float* __restrict__ Wt1, const float* __restrict__ bt1,
    const float* __restrict__ Wt2, const float* __restrict__ bt2,
    const float* __restrict__ Wt3, const float* __restrict__ bt3,
    const float* __restrict__ W1, int M)
{
    __shared__ float sW[4 * D * D];
    __shared__ float sB[3 * D];
    int tid = threadIdx.x;
    for (int t = tid; t < D * D; t += 256) {
        sW[t] = Wt1[t]; sW[256 + t] = Wt2[t]; sW[512 + t] = Wt3[t];
        sW[768 + t] = W1[t];
    }
    if (tid < D) { sB[tid] = bt1[tid]; sB[16 + tid] = bt2[tid]; sB[32 + tid] = bt3[tid]; }
    __syncthreads();

    int lane = tid & 31, j = lane & 15, half = lane >> 4;
    int i = blockIdx.x * 16 + (tid >> 5) * 2 + half;
    bool valid = i < M;
    int ii = valid ? i : M - 1;

    float v = atom_types[ii * D + j];
#pragma unroll
    for (int l = 0; l < 3; l++) {
        float a = sB[l * 16 + j];
#pragma unroll
        for (int kk = 0; kk < D; kk++)
            a = fmaf(__shfl_sync(FULL, v, kk, 16), sW[l * 256 + kk * D + j], a);
        v = a > 0.f ? a : 0.2f * a;
    }
    // u_j = sum_kk t_kk * W1[kk][j]
    float u = 0.f;
#pragma unroll
    for (int kk = 0; kk < D; kk++)
        u = fmaf(__shfl_sync(FULL, v, kk, 16), sW[768 + kk * D + j], u);

    if (valid) {
        g_u[i * D + j] = u;
        if (j == 0) {
            float x = atom_xyz[i * 3 + 0], y = atom_xyz[i * 3 + 1], z = atom_xyz[i * 3 + 2];
            g_atoms[i] = make_float4(x, y, z, x * x + y * y + z * z);
            int cx = min(max((int)floorf((x - GLO) / HCELL), 0), G - 1);
            int cy = min(max((int)floorf((y - GLO) / HCELL), 0), G - 1);
            int cz = min(max((int)floorf((z - GLO) / HCELL), 0), G - 1);
            int cell = (cz * G + cy) * G + cx;
            g_cellid[i] = cell;
            atomicAdd(&g_hist[cell], 1);
        }
    }
}

// ---------------------------------------------------------------------------
// scan: exclusive prefix over NCELLS histogram -> cellstart (+cursor copy)
// one block of 1024 threads, 14 elements per thread.
// ---------------------------------------------------------------------------
__global__ __launch_bounds__(1024) void scan_kernel()
{
    __shared__ int wsum[32];
    const int PER = 14;
    int tid = threadIdx.x, lane = tid & 31, wid = tid >> 5;
    int base = tid * PER;
    int loc[PER];
    int s = 0;
#pragma unroll
    for (int q = 0; q < PER; q++) {
        loc[q] = s;
        int idx = base + q;
        s += (idx < NCELLS) ? g_hist[idx] : 0;
    }
    int v = s;
#pragma unroll
    for (int o = 1; o < 32; o <<= 1) {
        int t = __shfl_up_sync(FULL, v, o);
        if (lane >= o) v += t;
    }
    if (lane == 31) wsum[wid] = v;
    __syncthreads();
    if (tid < 32) {
        int t = wsum[tid];
#pragma unroll
        for (int o = 1; o < 32; o <<= 1) {
            int x = __shfl_up_sync(FULL, t, o);
            if (tid >= o) t += x;
        }
        wsum[tid] = t;
    }
    __syncthreads();
    int excl = (v - s) + (wid > 0 ? wsum[wid - 1] : 0);
#pragma unroll
    for (int q = 0; q < PER; q++) {
        int idx = base + q;
        if (idx < NCELLS) {
            g_cellstart[idx] = excl + loc[q];
            g_cursor[idx]    = excl + loc[q];
        }
    }
    if (tid == 1023) g_cellstart[NCELLS] = excl + s;
}

// ---------------------------------------------------------------------------
__global__ __launch_bounds__(256) void scatter_kernel(int M)
{
    int a = blockIdx.x * 256 + threadIdx.x;
    if (a >= M) return;
    int cell = g_cellid[a];
    int pos = atomicAdd(&g_cursor[cell], 1);
    g_satoms[pos] = g_atoms[a];
    g_sorig[pos]  = a;
}

// ---------------------------------------------------------------------------
// knn: warp per point, expanding Chebyshev shells over the grid.
// Warp-collective sorted top-16 (lanes 0-15), packed (key<<32|origIdx) for
// exact JAX tie-break. Terminates when 16th-best strictly beats the
// box-boundary distance bound (faces at grid edge => +inf).
// ---------------------------------------------------------------------------
__global__ __launch_bounds__(256) void knn_kernel(const float* __restrict__ xyz, int N)
{
    int w = (blockIdx.x * 256 + threadIdx.x) >> 5;
    int lane = threadIdx.x & 31;
    if (w >= N) return;

    const float px = xyz[w * 3 + 0], py = xyz[w * 3 + 1], pz = xyz[w * 3 + 2];
    const float cx = -2.f * px, cy = -2.f * py, cz = -2.f * pz;
    const float pn = px * px + py * py + pz * pz;

    int cix = min(max((int)floorf((px - GLO) / HCELL), 0), G - 1);
    int ciy = min(max((int)floorf((py - GLO) / HCELL), 0), G - 1);
    int ciz = min(max((int)floorf((pz - GLO) / HCELL), 0), G - 1);

    unsigned long long lst = ~0ULL, tau = ~0ULL;
    int cnt = 0;

    for (int r = 0; r <= G; r++) {
        if (r > 0 && cnt >= KNN) {
            int q = r - 1;
            float bd = 3.0e38f;
            if (cix - q > 0)     bd = fminf(bd, px - (GLO + (cix - q) * HCELL));
            if (cix + q < G - 1) bd = fminf(bd, (GLO + (cix + q + 1) * HCELL) - px);
            if (ciy - q > 0)     bd = fminf(bd, py - (GLO + (ciy - q) * HCELL));
            if (ciy + q < G - 1) bd = fminf(bd, (GLO + (ciy + q + 1) * HCELL) - py);
            if (ciz - q > 0)     bd = fminf(bd, pz - (GLO + (ciz - q) * HCELL));
            if (ciz + q < G - 1) bd = fminf(bd, (GLO + (ciz + q + 1) * HCELL) - pz);
            float lim = bd * bd - pn;
            if ((unsigned)(tau >> 32) < fkey(lim)) break;
        }
        // scan shell of Chebyshev radius exactly r
        for (int dz = -r; dz <= r; dz++) {
            int z = ciz + dz;
            if (z < 0 || z >= G) continue;
            for (int dy = -r; dy <= r; dy++) {
                int y = ciy + dy;
                if (y < 0 || y >= G) continue;
                bool edge = (dz == -r || dz == r || dy == -r || dy == r || r == 0);
                int xstep = edge ? 1 : 2 * r;
                for (int dx = -r; dx <= r; dx += xstep) {
                    int x = cix + dx;
                    if (x < 0 || x >= G) continue;
                    int cell = (z * G + y) * G + x;
                    int s0 = g_cellstart[cell];
                    int e0 = g_cellstart[cell + 1];
                    cnt += e0 - s0;
                    for (int a0 = s0; a0 < e0; a0 += 32) {
                        int a = a0 + lane;
                        unsigned long long c = ~0ULL;
                        if (a < e0) {
                            float4 at = g_satoms[a];
                            int orig = g_sorig[a];
                            float s = fmaf(cx, at.x, at.w);
                            s = fmaf(cy, at.y, s);
                            s = fmaf(cz, at.z, s);
                            c = ((unsigned long long)fkey(s) << 32) | (unsigned)orig;
                        }
                        unsigned ball = __ballot_sync(FULL, c < tau);
                        while (ball) {
                            int src = __ffs(ball) - 1;
                            ball &= ball - 1;
                            unsigned long long cc = __shfl_sync(FULL, c, src);
                            if (cc < tau) {
                                unsigned long long up = __shfl_up_sync(FULL, lst, 1);
                                bool gt = lst > cc;
                                unsigned gm = __ballot_sync(FULL, gt);
                                int pos = __ffs(gm) - 1;
                                if (gt) lst = (lane == pos) ? cc : up;
                                tau = __shfl_sync(FULL, lst, 15);
                            }
                        }
                    }
                }
            }
        }
    }

    if (lane < KNN) {
        int ai = (int)(unsigned)(lst & 0xffffffffu);
        float4 at = g_atoms[ai];
        float dx = px - at.x, dy = py - at.y, dz = pz - at.z;
        float dd = fmaf(dz, dz, fmaf(dy, dy, dx * dx));
        g_idx[w * KNN + lane]  = ai;
        g_rinv[w * KNN + lane] = 1.0f / dd;
    }
}

// ---------------------------------------------------------------------------
// stats1: h1 = leaky(u[ai] + rv*W1r + b1); BN1 sum/sumsq; ticket finalize.
// Grid-stride over rows, 2048 blocks. Lane j owns channel j; 2 rows/warp.
// ---------------------------------------------------------------------------
__global__ __launch_bounds__(256) void stats1_kernel(
    const float* __restrict__ W1, const float* __restrict__ b1,
    const float* __restrict__ g1, const float* __restrict__ be1,
    int N, float inv_n)
{
    __shared__ float red[8 * 32];
    __shared__ float tot[32];
    __shared__ int   ticket;
    int tid = threadIdx.x;
    int lane = tid & 31, j = lane & 15;
    float b1j = b1[j];
    float wrj = W1[D * D + j];

    float s = 0.f, q = 0.f;
    int NR = N * KNN;
    for (int row = blockIdx.x * 16 + (tid >> 4); row < NR; row += gridDim.x * 16) {
        int   ai = g_idx[row];
        float rv = g_rinv[row];
        float a = g_u[ai * D + j] + b1j;
        a = fmaf(rv, wrj, a);
        float h = a > 0.f ? a : 0.2f * a;
        s += h;
        q = fmaf(h, h, q);
    }
    s += __shfl_xor_sync(FULL, s, 16);
    q += __shfl_xor_sync(FULL, q, 16);
    if (lane < 16) { red[(tid >> 5) * 32 + j] = s; red[(tid >> 5) * 32 + 16 + j] = q; }
    __syncthreads();
    if (tid < 32) {
        float acc = 0.f;
#pragma unroll
        for (int ww = 0; ww < 8; ww++) acc += red[ww * 32 + tid];
        g_part1[blockIdx.x * 32 + tid] = acc;
    }
    __threadfence();
    __syncthreads();
    if (tid == 0) ticket = atomicAdd(&g_ctr1, 1);
    __syncthreads();
    if (ticket == gridDim.x - 1) {
        int c = tid & 31, sl = tid >> 5;
        float acc = 0.f;
        for (int b = sl; b < (int)gridDim.x; b += 8) acc += g_part1[b * 32 + c];
        __syncthreads();
        red[sl * 32 + c] = acc;
        __syncthreads();
        if (tid < 32) {
            float t2 = 0.f;
#pragma unroll
            for (int ww = 0; ww < 8; ww++) t2 += red[ww * 32 + tid];
            tot[tid] = t2;
        }
        __syncthreads();
        if (tid < 16) {
            float mean = tot[tid] * inv_n;
            float var  = tot[16 + tid] * inv_n - mean * mean;
            float sc   = g1[tid] * rsqrtf(var + 1e-5f);
            g_bn[tid]      = sc;
            g_bn[16 + tid] = be1[tid] - mean * sc;
        }
        if (tid == 0) g_ctr1 = 0;
    }
}

// ---------------------------------------------------------------------------
// stats2: per point: h1 from u, y=bn1(h1), conv2 (16 shfl), h2;
// S1,S2 stores; BN2 sum/sumsq with ticket finalize.
// ---------------------------------------------------------------------------
__global__ __launch_bounds__(256) void stats2_kernel(
    const float* __restrict__ W1, const float* __restrict__ b1,
    const float* __restrict__ W2, const float* __restrict__ b2,
    const float* __restrict__ g2, const float* __restrict__ be2,
    int N, float inv_n)
{
    __shared__ float sW2[D * D];
    __shared__ float red[8 * 32];
    __shared__ float tot[32];
    __shared__ int   ticket;
    int tid = threadIdx.x;
    for (int t = tid; t < D * D; t += 256) sW2[t] = W2[t];
    __syncthreads();

    int lane = tid & 31, j = lane & 15, half = lane >> 4;
    int i = blockIdx.x * 16 + (tid >> 5) * 2 + half;
    bool valid = i < N;
    int ii = valid ? i : N - 1;
    float b1j = b1[j], b2j = b2[j];
    float wrj = W1[D * D + j];
    float sc1 = g_bn[j], sh1 = g_bn[16 + j];

    float S1 = 0.f, S2 = 0.f, Q2 = 0.f;
#pragma unroll 1
    for (int k = 0; k < KNN; k++) {
        int   ai = g_idx[ii * KNN + k];
        float rv = g_rinv[ii * KNN + k];
        float a = g_u[ai * D + j] + b1j;
        a = fmaf(rv, wrj, a);
        float h = a > 0.f ? a : 0.2f * a;
        S1 += h;
        float y = fmaf(h, sc1, sh1);
        float c = b2j;
#pragma unroll
        for (int kk = 0; kk < D; kk++)
            c = fmaf(__shfl_sync(FULL, y, kk, 16), sW2[kk * D + j], c);
        float h2 = c > 0.f ? c : 0.2f * c;
        S2 += h2;
        Q2 = fmaf(h2, h2, Q2);
    }
    if (valid) {
        g_S1[i * D + j] = S1;
        g_S2[i * D + j] = S2;
    } else { S2 = 0.f; Q2 = 0.f; }

    float s = S2 + __shfl_xor_sync(FULL, S2, 16);
    float q = Q2 + __shfl_xor_sync(FULL, Q2, 16);
    if (lane < 16) { red[(tid >> 5) * 32 + j] = s; red[(tid >> 5) * 32 + 16 + j] = q; }
    __syncthreads();
    if (tid < 32) {
        float acc = 0.f;
#pragma unroll
        for (int ww = 0; ww < 8; ww++) acc += red[ww * 32 + tid];
        g_part2[blockIdx.x * 32 + tid] = acc;
    }
    __threadfence();
    __syncthreads();
    if (tid == 0) ticket = atomicAdd(&g_ctr2, 1);
    __syncthreads();
    if (ticket == gridDim.x - 1) {
        int c = tid & 31, sl = tid >> 5;
        float acc = 0.f;
        for (int b = sl; b < (int)gridDim.x; b += 8) acc += g_part2[b * 32 + c];
        __syncthreads();
        red[sl * 32 + c] = acc;
        __syncthreads();
        if (tid < 32) {
            float t2 = 0.f;
#pragma unroll
            for (int ww = 0; ww < 8; ww++) t2 += red[ww * 32 + tid];
            tot[tid] = t2;
        }
        __syncthreads();
        if (tid < 16) {
            float mean = tot[tid] * inv_n;
            float var  = tot[16 + tid] * inv_n - mean * mean;
            float sc   = g2[tid] * rsqrtf(var + 1e-5f);
            g_bn[32 + tid] = sc;
            g_bn[48 + tid] = be2[tid] - mean * sc;
        }
        if (tid == 0) g_ctr2 = 0;
    }
}

// ---------------------------------------------------------------------------
// final: fx1 = sc1*S1 + K*sh1; fx2 = sc2*S2 + K*sh2; out=[fx1,fx2]@W3+b3.
// ---------------------------------------------------------------------------
__global__ __launch_bounds__(256) void final_kernel(
    const float* __restrict__ W3, const float* __restrict__ b3,
    float* __restrict__ out, int N)
{
    __shared__ float sW[2 * D * D];
    int tid = threadIdx.x;
    for (int t = tid; t < 2 * D * D; t += 256) sW[t] = W3[t];
    __syncthreads();

    int lane = tid & 31, j = lane & 15, half = lane >> 4;
    int i = blockIdx.x * 16 + (tid >> 5) * 2 + half;
    bool valid = i < N;
    int ii = valid ? i : N - 1;

    float fx1 = fmaf(g_S1[ii * D + j], g_bn[j],      (float)KNN * g_bn[16 + j]);
    float fx2 = fmaf(g_S2[ii * D + j], g_bn[32 + j], (float)KNN * g_bn[48 + j]);
    float o = b3[j];
#pragma unroll
    for (int kk = 0; kk < D; kk++)
        o = fmaf(__shfl_sync(FULL, fx1, kk, 16), sW[kk * D + j], o);
#pragma unroll
    for (int kk = 0; kk < D; kk++)
        o = fmaf(__shfl_sync(FULL, fx2, kk, 16), sW[(D + kk) * D + j], o);
    if (valid) out[i * D + j] = o;
}

// ---------------------------------------------------------------------------
extern "C" void kernel_launch(void* const* d_in, const int* in_sizes, int n_in,
                              void* d_out, int out_size)
{
    const float* xyz        = (const float*)d_in[0];
    const float* atom_xyz   = (const float*)d_in[1];
    const float* atom_types = (const float*)d_in[2];
    const float* Wt1 = (const float*)d_in[3];
    const float* bt1 = (const float*)d_in[4];
    const float* Wt2 = (const float*)d_in[5];
    const float* bt2 = (const float*)d_in[6];
    const float* Wt3 = (const float*)d_in[7];
    const float* bt3 = (const float*)d_in[8];
    const float* W1  = (const float*)d_in[9];
    const float* b1  = (const float*)d_in[10];
    const float* W2  = (const float*)d_in[11];
    const float* b2  = (const float*)d_in[12];
    const float* W3  = (const float*)d_in[13];
    const float* b3  = (const float*)d_in[14];
    const float* g1  = (const float*)d_in[15];
    const float* be1 = (const float*)d_in[16];
    const float* g2  = (const float*)d_in[17];
    const float* be2 = (const float*)d_in[18];

    int N = in_sizes[0] / 3;
    int M = in_sizes[1] / 3;
    float inv_n = 1.0f / (float)(N * KNN);

    zero_kernel<<<(NCELLS + 255) / 256, 256>>>();
    prep_kernel<<<(M + 15) / 16, 256>>>(atom_xyz, atom_types,
                                        Wt1, bt1, Wt2, bt2, Wt3, bt3, W1, M);
    scan_kernel<<<1, 1024>>>();
    scatter_kernel<<<(M + 255) / 256, 256>>>(M);

    knn_kernel<<<(N * 32 + 255) / 256, 256>>>(xyz, N);

    stats1_kernel<<<2048, 256>>>(W1, b1, g1, be1, N, inv_n);
    stats2_kernel<<<(N + 15) / 16, 256>>>(W1, b1, W2, b2, g2, be2, N, inv_n);
    final_kernel<<<(N + 15) / 16, 256>>>(W3, b3, (float*)d_out, N);
}

// round 13
// speedup vs baseline: 2.9646x; 1.0488x over previous
#include <cuda_runtime.h>
#include <math.h>

#define D    16
#define KNN  16
#define FULL 0xffffffffu

#define NMAX 30720
#define MMAX 8192

#define G      24
#define NCELLS (G * G * G)        // 13824
#define HCELL  0.4f
#define GLO    (-4.8f)

// ---- scratch (static device globals; no allocation anywhere) ----
__device__ float4 g_atoms[MMAX];          // x,y,z,||y||^2 (original order)
__device__ float  g_u[MMAX * D];          // t @ W1[0:16,:]  (original order)
__device__ int    g_cellid[MMAX];
__device__ int    g_hist[NCELLS];
__device__ int    g_cellstart[NCELLS + 1];
__device__ int    g_cursor[NCELLS];
__device__ float4 g_satoms[MMAX];         // sorted by cell
__device__ int    g_sorig[MMAX];          // sorted -> original idx
// point sort
__device__ int    g_pcell[NMAX];
__device__ int    g_phist[NCELLS];
__device__ int    g_pstart[NCELLS + 1];
__device__ int    g_pcursor[NCELLS];
__device__ int    g_psort[NMAX];          // sorted point indices
// pipeline
__device__ int    g_idx[NMAX * KNN];
__device__ float  g_rinv[NMAX * KNN];
__device__ float  g_S1[NMAX * D];
__device__ float  g_S2[NMAX * D];
__device__ float  g_part1[2048 * 32];
__device__ float  g_part2[2048 * 32];
__device__ float  g_bn[64];               // sc1,sh1,sc2,sh2
__device__ int    g_ctr1 = 0;
__device__ int    g_ctr2 = 0;

__device__ __forceinline__ unsigned fkey(float s) {
    unsigned b = __float_as_uint(s);
    return b ^ (((unsigned)((int)b >> 31)) | 0x80000000u);   // monotonic map
}

// ---------------------------------------------------------------------------
__global__ __launch_bounds__(256) void zero_kernel()
{
    int i = blockIdx.x * 256 + threadIdx.x;
    if (i < NCELLS) g_hist[i] = 0;
    else if (i < 2 * NCELLS) g_phist[i - NCELLS] = 0;
}

// ---------------------------------------------------------------------------
// prep: atom MLP -> t; u = t @ W1[0:16,:]; pack coords/norm; cell id + hist.
// ---------------------------------------------------------------------------
__global__ __launch_bounds__(256) void prep_kernel(
    const float* __restrict__ atom_xyz, const float* __restrict__ atom_types,
    const float* __restrict__ Wt1, const float* __restrict__ bt1,
    const float* __restrict__ Wt2, const float* __restrict__ bt2,
    const float* __restrict__ Wt3, const float* __restrict__ bt3,
    const float* __restrict__ W1, int M)
{
    __shared__ float sW[4 * D * D];
    __shared__ float sB[3 * D];
    int tid = threadIdx.x;
    for (int t = tid; t < D * D; t += 256) {
        sW[t] = Wt1[t]; sW[256 + t] = Wt2[t]; sW[512 + t] = Wt3[t];
        sW[768 + t] = W1[t];
    }
    if (tid < D) { sB[tid] = bt1[tid]; sB[16 + tid] = bt2[tid]; sB[32 + tid] = bt3[tid]; }
    __syncthreads();

    int lane = tid & 31, j = lane & 15, half = lane >> 4;
    int i = blockIdx.x * 16 + (tid >> 5) * 2 + half;
    bool valid = i < M;
    int ii = valid ? i : M - 1;

    float v = atom_types[ii * D + j];
#pragma unroll
    for (int l = 0; l < 3; l++) {
        float a = sB[l * 16 + j];
#pragma unroll
        for (int kk = 0; kk < D; kk++)
            a = fmaf(__shfl_sync(FULL, v, kk, 16), sW[l * 256 + kk * D + j], a);
        v = a > 0.f ? a : 0.2f * a;
    }
    float u = 0.f;
#pragma unroll
    for (int kk = 0; kk < D; kk++)
        u = fmaf(__shfl_sync(FULL, v, kk, 16), sW[768 + kk * D + j], u);

    if (valid) {
        g_u[i * D + j] = u;
        if (j == 0) {
            float x = atom_xyz[i * 3 + 0], y = atom_xyz[i * 3 + 1], z = atom_xyz[i * 3 + 2];
            g_atoms[i] = make_float4(x, y, z, x * x + y * y + z * z);
            int cx = min(max((int)floorf((x - GLO) / HCELL), 0), G - 1);
            int cy = min(max((int)floorf((y - GLO) / HCELL), 0), G - 1);
            int cz = min(max((int)floorf((z - GLO) / HCELL), 0), G - 1);
            int cell = (cz * G + cy) * G + cx;
            g_cellid[i] = cell;
            atomicAdd(&g_hist[cell], 1);
        }
    }
}

// ---------------------------------------------------------------------------
__global__ __launch_bounds__(256) void pcell_kernel(const float* __restrict__ xyz, int N)
{
    int i = blockIdx.x * 256 + threadIdx.x;
    if (i >= N) return;
    float x = xyz[i * 3 + 0], y = xyz[i * 3 + 1], z = xyz[i * 3 + 2];
    int cx = min(max((int)floorf((x - GLO) / HCELL), 0), G - 1);
    int cy = min(max((int)floorf((y - GLO) / HCELL), 0), G - 1);
    int cz = min(max((int)floorf((z - GLO) / HCELL), 0), G - 1);
    int cell = (cz * G + cy) * G + cx;
    g_pcell[i] = cell;
    atomicAdd(&g_phist[cell], 1);
}

// ---------------------------------------------------------------------------
// scan: blockIdx 0 = atom hist, blockIdx 1 = point hist.
// ---------------------------------------------------------------------------
__global__ __launch_bounds__(1024) void scan_kernel()
{
    const int* hist = blockIdx.x ? g_phist : g_hist;
    int* start  = blockIdx.x ? g_pstart  : g_cellstart;
    int* cursor = blockIdx.x ? g_pcursor : g_cursor;

    __shared__ int wsum[32];
    const int PER = 14;
    int tid = threadIdx.x, lane = tid & 31, wid = tid >> 5;
    int base = tid * PER;
    int loc[PER];
    int s = 0;
#pragma unroll
    for (int q = 0; q < PER; q++) {
        loc[q] = s;
        int idx = base + q;
        s += (idx < NCELLS) ? hist[idx] : 0;
    }
    int v = s;
#pragma unroll
    for (int o = 1; o < 32; o <<= 1) {
        int t = __shfl_up_sync(FULL, v, o);
        if (lane >= o) v += t;
    }
    if (lane == 31) wsum[wid] = v;
    __syncthreads();
    if (tid < 32) {
        int t = wsum[tid];
#pragma unroll
        for (int o = 1; o < 32; o <<= 1) {
            int x = __shfl_up_sync(FULL, t, o);
            if (tid >= o) t += x;
        }
        wsum[tid] = t;
    }
    __syncthreads();
    int excl = (v - s) + (wid > 0 ? wsum[wid - 1] : 0);
#pragma unroll
    for (int q = 0; q < PER; q++) {
        int idx = base + q;
        if (idx < NCELLS) {
            start[idx]  = excl + loc[q];
            cursor[idx] = excl + loc[q];
        }
    }
    if (tid == 1023) start[NCELLS] = excl + s;
}

// ---------------------------------------------------------------------------
__global__ __launch_bounds__(256) void scatter_kernel(int M, int N)
{
    int a = blockIdx.x * 256 + threadIdx.x;
    if (a < M) {
        int cell = g_cellid[a];
        int pos = atomicAdd(&g_cursor[cell], 1);
        g_satoms[pos] = g_atoms[a];
        g_sorig[pos]  = a;
    }
    int p = a - ((M + 255) & ~255);
    // points handled by separate range of blocks
    if (p >= 0 && p < N) {
        int cell = g_pcell[p];
        int pos = atomicAdd(&g_pcursor[cell], 1);
        g_psort[pos] = p;
    }
}

// ---------------------------------------------------------------------------
// knn v4: block per cell; each LANE owns one point of the cell; candidate
// stream (expanding cell-cube shells) is identical for all lanes -> broadcast
// loads. Per-lane register sorted top-16 keys via min/max network. Second
// pass re-enumerates shells to recover indices (<tau always; ==tau filled
// up to budget). Exact termination via per-lane cube-boundary bound.
// ---------------------------------------------------------------------------
__global__ __launch_bounds__(128) void knn_kernel(const float* __restrict__ xyz)
{
    int cell = blockIdx.x;
    int p0 = g_pstart[cell], p1 = g_pstart[cell + 1];
    if (p0 == p1) return;

    int cix = cell % G, ciy = (cell / G) % G, ciz = cell / (G * G);
    int lane = threadIdx.x & 31;
    int wid  = threadIdx.x >> 5;

    for (int pb = p0 + wid * 32; pb < p1; pb += 128) {
        int pi = pb + lane;
        bool valid = pi < p1;
        int pt = valid ? g_psort[pi] : 0;
        float px = 0.f, py = 0.f, pz = 0.f;
        if (valid) { px = xyz[pt * 3 + 0]; py = xyz[pt * 3 + 1]; pz = xyz[pt * 3 + 2]; }
        const float cxm = -2.f * px, cym = -2.f * py, czm = -2.f * pz;
        const float pn = px * px + py * py + pz * pz;

        unsigned k[16];
#pragma unroll
        for (int j = 0; j < 16; j++) k[j] = 0xFFFFFFFFu;

        int rfinal = 0;
        for (int r = 0; r <= G; r++) {
            if (r > 0) {
                int q = r - 1;
                float bd = 3.0e38f;
                if (cix - q > 0)     bd = fminf(bd, px - (GLO + (cix - q) * HCELL));
                if (cix + q < G - 1) bd = fminf(bd, (GLO + (cix + q + 1) * HCELL) - px);
                if (ciy - q > 0)     bd = fminf(bd, py - (GLO + (ciy - q) * HCELL));
                if (ciy + q < G - 1) bd = fminf(bd, (GLO + (ciy + q + 1) * HCELL) - py);
                if (ciz - q > 0)     bd = fminf(bd, pz - (GLO + (ciz - q) * HCELL));
                if (ciz + q < G - 1) bd = fminf(bd, (GLO + (ciz + q + 1) * HCELL) - pz);
                float lim = bd * bd - pn;
                bool done = !valid || (k[15] != 0xFFFFFFFFu && k[15] < fkey(lim));
                if (__all_sync(FULL, done)) break;
            }
            rfinal = r;
            // ---- scan shell of Chebyshev radius exactly r ----
            for (int dz = -r; dz <= r; dz++) {
                int z = ciz + dz;
                if ((unsigned)z >= (unsigned)G) continue;
                for (int dy = -r; dy <= r; dy++) {
                    int y = ciy + dy;
                    if ((unsigned)y >= (unsigned)G) continue;
                    int rowb = (z * G + y) * G;
                    bool fullrow = (dz == -r || dz == r || dy == -r || dy == r);
                    int s0, e0, s1 = 0, e1 = 0;
                    if (fullrow) {
                        int x0 = max(cix - r, 0), x1 = min(cix + r, G - 1);
                        s0 = g_cellstart[rowb + x0];
                        e0 = g_cellstart[rowb + x1 + 1];
                    } else {
                        int xl = cix - r, xr = cix + r;
                        if (xl >= 0) { s0 = g_cellstart[rowb + xl]; e0 = g_cellstart[rowb + xl + 1]; }
                        else         { s0 = 0; e0 = 0; }
                        if (xr < G)  { s1 = g_cellstart[rowb + xr]; e1 = g_cellstart[rowb + xr + 1]; }
                    }
#pragma unroll 1
                    for (int seg = 0; seg < 2; seg++) {
                        int ss = seg ? s1 : s0, ee = seg ? e1 : e0;
                        for (int a0 = ss; a0 < ee; a0 += 4) {
                            int n = ee - a0;
                            float4 at0 = g_satoms[a0];
                            float4 at1 = (n > 1) ? g_satoms[a0 + 1] : at0;
                            float4 at2 = (n > 2) ? g_satoms[a0 + 2] : at0;
                            float4 at3 = (n > 3) ? g_satoms[a0 + 3] : at0;
                            unsigned vq[4]; bool iq[4];
#pragma unroll
                            for (int q = 0; q < 4; q++) {
                                float4 at = (q == 0) ? at0 : (q == 1) ? at1 : (q == 2) ? at2 : at3;
                                float s = fmaf(cxm, at.x, at.w);
                                s = fmaf(cym, at.y, s);
                                s = fmaf(czm, at.z, s);
                                vq[q] = (q < n) ? fkey(s) : 0xFFFFFFFFu;
                                iq[q] = valid && (vq[q] < k[15]);
                            }
                            if (__any_sync(FULL, iq[0] | iq[1] | iq[2] | iq[3])) {
#pragma unroll
                                for (int q = 0; q < 4; q++) {
                                    if (__any_sync(FULL, iq[q])) {
                                        unsigned vv = iq[q] ? vq[q] : 0xFFFFFFFFu;
#pragma unroll
                                        for (int j = 15; j >= 1; j--) {
                                            unsigned t = vv < k[j - 1] ? k[j - 1] : vv;
                                            k[j] = vv < k[j] ? t : k[j];
                                        }
                                        k[0] = vv < k[0] ? vv : k[0];
                                    }
                                }
                            }
                        }
                    }
                }
            }
        }

        // ---- pass 2: recover indices ----
        unsigned tau = k[15];
        int c_less = 0;
#pragma unroll
        for (int j = 0; j < 15; j++) c_less += (k[j] < tau) ? 1 : 0;
        int budget = 16 - c_less;
        int c_lt = 0, c_eq = 0;

        for (int r = 0; r <= rfinal; r++) {
            for (int dz = -r; dz <= r; dz++) {
                int z = ciz + dz;
                if ((unsigned)z >= (unsigned)G) continue;
                for (int dy = -r; dy <= r; dy++) {
                    int y = ciy + dy;
                    if ((unsigned)y >= (unsigned)G) continue;
                    int rowb = (z * G + y) * G;
                    bool fullrow = (dz == -r || dz == r || dy == -r || dy == r);
                    int s0, e0, s1 = 0, e1 = 0;
                    if (fullrow) {
                        int x0 = max(cix - r, 0), x1 = min(cix + r, G - 1);
                        s0 = g_cellstart[rowb + x0];
                        e0 = g_cellstart[rowb + x1 + 1];
                    } else {
                        int xl = cix - r, xr = cix + r;
                        if (xl >= 0) { s0 = g_cellstart[rowb + xl]; e0 = g_cellstart[rowb + xl + 1]; }
                        else         { s0 = 0; e0 = 0; }
                        if (xr < G)  { s1 = g_cellstart[rowb + xr]; e1 = g_cellstart[rowb + xr + 1]; }
                    }
#pragma unroll 1
                    for (int seg = 0; seg < 2; seg++) {
                        int ss = seg ? s1 : s0, ee = seg ? e1 : e0;
#pragma unroll 4
                        for (int a = ss; a < ee; a++) {
                            float4 at = g_satoms[a];
                            float s = fmaf(cxm, at.x, at.w);
                            s = fmaf(cym, at.y, s);
                            s = fmaf(czm, at.z, s);
                            unsigned v = fkey(s);
                            bool lt = valid && v < tau;
                            bool eq = valid && v == tau && c_eq < budget;
                            if (lt | eq) {
                                int slot = lt ? c_lt : (c_less + c_eq);
                                if (lt) c_lt++; else c_eq++;
                                int orig = g_sorig[a];
                                float dx = px - at.x, dyy = py - at.y, dzz = pz - at.z;
                                float dd = fmaf(dzz, dzz, fmaf(dyy, dyy, dx * dx));
                                g_idx[pt * KNN + slot]  = orig;
                                g_rinv[pt * KNN + slot] = 1.0f / dd;
                            }
                        }
                    }
                }
            }
        }
    }
}

// ---------------------------------------------------------------------------
// stats1: h1 = leaky(u[ai] + rv*W1r + b1); BN1 sum/sumsq; ticket finalize.
// ---------------------------------------------------------------------------
__global__ __launch_bounds__(256) void stats1_kernel(
    const float* __restrict__ W1, const float* __restrict__ b1,
    const float* __restrict__ g1, const float* __restrict__ be1,
    int N, float inv_n)
{
    __shared__ float red[8 * 32];
    __shared__ float tot[32];
    __shared__ int   ticket;
    int tid = threadIdx.x;
    int lane = tid & 31, j = lane & 15;
    float b1j = b1[j];
    float wrj = W1[D * D + j];

    float s = 0.f, q = 0.f;
    int NR = N * KNN;
    for (int row = blockIdx.x * 16 + (tid >> 4); row < NR; row += gridDim.x * 16) {
        int   ai = g_idx[row];
        float rv = g_rinv[row];
        float a = g_u[ai * D + j] + b1j;
        a = fmaf(rv, wrj, a);
        float h = a > 0.f ? a : 0.2f * a;
        s += h;
        q = fmaf(h, h, q);
    }
    s += __shfl_xor_sync(FULL, s, 16);
    q += __shfl_xor_sync(FULL, q, 16);
    if (lane < 16) { red[(tid >> 5) * 32 + j] = s; red[(tid >> 5) * 32 + 16 + j] = q; }
    __syncthreads();
    if (tid < 32) {
        float acc = 0.f;
#pragma unroll
        for (int ww = 0; ww < 8; ww++) acc += red[ww * 32 + tid];
        g_part1[blockIdx.x * 32 + tid] = acc;
    }
    __threadfence();
    __syncthreads();
    if (tid == 0) ticket = atomicAdd(&g_ctr1, 1);
    __syncthreads();
    if (ticket == gridDim.x - 1) {
        int c = tid & 31, sl = tid >> 5;
        float acc = 0.f;
        for (int b = sl; b < (int)gridDim.x; b += 8) acc += g_part1[b * 32 + c];
        __syncthreads();
        red[sl * 32 + c] = acc;
        __syncthreads();
        if (tid < 32) {
            float t2 = 0.f;
#pragma unroll
            for (int ww = 0; ww < 8; ww++) t2 += red[ww * 32 + tid];
            tot[tid] = t2;
        }
        __syncthreads();
        if (tid < 16) {
            float mean = tot[tid] * inv_n;
            float var  = tot[16 + tid] * inv_n - mean * mean;
            float sc   = g1[tid] * rsqrtf(var + 1e-5f);
            g_bn[tid]      = sc;
            g_bn[16 + tid] = be1[tid] - mean * sc;
        }
        if (tid == 0) g_ctr1 = 0;
    }
}

// ---------------------------------------------------------------------------
// stats2: per point with software-pipelined neighbor loads.
// ---------------------------------------------------------------------------
__global__ __launch_bounds__(256) void stats2_kernel(
    const float* __restrict__ W1, const float* __restrict__ b1,
    const float* __restrict__ W2, const float* __restrict__ b2,
    const float* __restrict__ g2, const float* __restrict__ be2,
    int N, float inv_n)
{
    __shared__ float sW2[D * D];
    __shared__ float red[8 * 32];
    __shared__ float tot[32];
    __shared__ int   ticket;
    int tid = threadIdx.x;
    for (int t = tid; t < D * D; t += 256) sW2[t] = W2[t];
    __syncthreads();

    int lane = tid & 31, j = lane & 15, half = lane >> 4;
    int i = blockIdx.x * 16 + (tid >> 5) * 2 + half;
    bool valid = i < N;
    int ii = valid ? i : N - 1;
    float b1j = b1[j], b2j = b2[j];
    float wrj = W1[D * D + j];
    float sc1 = g_bn[j], sh1 = g_bn[16 + j];

    float S1 = 0.f, S2 = 0.f, Q2 = 0.f;
    int base = ii * KNN;
    float rv = g_rinv[base];
    float uj = g_u[g_idx[base] * D + j];
#pragma unroll 1
    for (int k = 0; k < KNN; k++) {
        float rv_n = 0.f, uj_n = 0.f;
        if (k + 1 < KNN) {
            rv_n = g_rinv[base + k + 1];
            uj_n = g_u[g_idx[base + k + 1] * D + j];
        }
        float a = uj + b1j;
        a = fmaf(rv, wrj, a);
        float h = a > 0.f ? a : 0.2f * a;
        S1 += h;
        float y = fmaf(h, sc1, sh1);
        float c = b2j;
#pragma unroll
        for (int kk = 0; kk < D; kk++)
            c = fmaf(__shfl_sync(FULL, y, kk, 16), sW2[kk * D + j], c);
        float h2 = c > 0.f ? c : 0.2f * c;
        S2 += h2;
        Q2 = fmaf(h2, h2, Q2);
        rv = rv_n; uj = uj_n;
    }
    if (valid) {
        g_S1[i * D + j] = S1;
        g_S2[i * D + j] = S2;
    } else { S2 = 0.f; Q2 = 0.f; }

    float s = S2 + __shfl_xor_sync(FULL, S2, 16);
    float q = Q2 + __shfl_xor_sync(FULL, Q2, 16);
    if (lane < 16) { red[(tid >> 5) * 32 + j] = s; red[(tid >> 5) * 32 + 16 + j] = q; }
    __syncthreads();
    if (tid < 32) {
        float acc = 0.f;
#pragma unroll
        for (int ww = 0; ww < 8; ww++) acc += red[ww * 32 + tid];
        g_part2[blockIdx.x * 32 + tid] = acc;
    }
    __threadfence();
    __syncthreads();
    if (tid == 0) ticket = atomicAdd(&g_ctr2, 1);
    __syncthreads();
    if (ticket == gridDim.x - 1) {
        int c = tid & 31, sl = tid >> 5;
        float acc = 0.f;
        for (int b = sl; b < (int)gridDim.x; b += 8) acc += g_part2[b * 32 + c];
        __syncthreads();
        red[sl * 32 + c] = acc;
        __syncthreads();
        if (tid < 32) {
            float t2 = 0.f;
#pragma unroll
            for (int ww = 0; ww < 8; ww++) t2 += red[ww * 32 + tid];
            tot[tid] = t2;
        }
        __syncthreads();
        if (tid < 16) {
            float mean = tot[tid] * inv_n;
            float var  = tot[16 + tid] * inv_n - mean * mean;
            float sc   = g2[tid] * rsqrtf(var + 1e-5f);
            g_bn[32 + tid] = sc;
            g_bn[48 + tid] = be2[tid] - mean * sc;
        }
        if (tid == 0) g_ctr2 = 0;
    }
}

// ---------------------------------------------------------------------------
__global__ __launch_bounds__(256) void final_kernel(
    const float* __restrict__ W3, const float* __restrict__ b3,
    float* __restrict__ out, int N)
{
    __shared__ float sW[2 * D * D];
    int tid = threadIdx.x;
    for (int t = tid; t < 2 * D * D; t += 256) sW[t] = W3[t];
    __syncthreads();

    int lane = tid & 31, j = lane & 15, half = lane >> 4;
    int i = blockIdx.x * 16 + (tid >> 5) * 2 + half;
    bool valid = i < N;
    int ii = valid ? i : N - 1;

    float fx1 = fmaf(g_S1[ii * D + j], g_bn[j],      (float)KNN * g_bn[16 + j]);
    float fx2 = fmaf(g_S2[ii * D + j], g_bn[32 + j], (float)KNN * g_bn[48 + j]);
    float o = b3[j];
#pragma unroll
    for (int kk = 0; kk < D; kk++)
        o = fmaf(__shfl_sync(FULL, fx1, kk, 16), sW[kk * D + j], o);
#pragma unroll
    for (int kk = 0; kk < D; kk++)
        o = fmaf(__shfl_sync(FULL, fx2, kk, 16), sW[(D + kk) * D + j], o);
    if (valid) out[i * D + j] = o;
}

// ---------------------------------------------------------------------------
extern "C" void kernel_launch(void* const* d_in, const int* in_sizes, int n_in,
                              void* d_out, int out_size)
{
    const float* xyz        = (const float*)d_in[0];
    const float* atom_xyz   = (const float*)d_in[1];
    const float* atom_types = (const float*)d_in[2];
    const float* Wt1 = (const float*)d_in[3];
    const float* bt1 = (const float*)d_in[4];
    const float* Wt2 = (const float*)d_in[5];
    const float* bt2 = (const float*)d_in[6];
    const float* Wt3 = (const float*)d_in[7];
    const float* bt3 = (const float*)d_in[8];
    const float* W1  = (const float*)d_in[9];
    const float* b1  = (const float*)d_in[10];
    const float* W2  = (const float*)d_in[11];
    const float* b2  = (const float*)d_in[12];
    const float* W3  = (const float*)d_in[13];
    const float* b3  = (const float*)d_in[14];
    const float* g1  = (const float*)d_in[15];
    const float* be1 = (const float*)d_in[16];
    const float* g2  = (const float*)d_in[17];
    const float* be2 = (const float*)d_in[18];

    int N = in_sizes[0] / 3;
    int M = in_sizes[1] / 3;
    float inv_n = 1.0f / (float)(N * KNN);

    zero_kernel<<<(2 * NCELLS + 255) / 256, 256>>>();
    prep_kernel<<<(M + 15) / 16, 256>>>(atom_xyz, atom_types,
                                        Wt1, bt1, Wt2, bt2, Wt3, bt3, W1, M);
    pcell_kernel<<<(N + 255) / 256, 256>>>(xyz, N);
    scan_kernel<<<2, 1024>>>();
    {
        int mpad = (M + 255) & ~255;
        scatter_kernel<<<(mpad + N + 255) / 256, 256>>>(M, N);
    }

    knn_kernel<<<NCELLS, 128>>>(xyz);

    stats1_kernel<<<2048, 256>>>(W1, b1, g1, be1, N, inv_n);
    stats2_kernel<<<(N + 15) / 16, 256>>>(W1, b1, W2, b2, g2, be2, N, inv_n);
    final_kernel<<<(N + 15) / 16, 256>>>(W3, b3, (float*)d_out, N);
}